// round 12
// baseline (speedup 1.0000x reference)
#include <cuda_runtime.h>
#include <cuda_fp16.h>
#include <cstdint>

// Problem constants
#define NROWS 32768
#define DDIM  512
#define CB    16     // codebooks
#define KC    16     // codewords per codebook
#define SV    32     // subvector length
#define MOUT  1024

// ---- device scratch (no allocations allowed) ----
__device__ float          g_pn[CB * KC];            // ||proto||^2
__device__ float          g_bsums[1024];            // per-block X sums
__device__ float          g_scale;                  // mean(X)
__device__ unsigned int   g_ctr;                    // encode completion ticket
__device__ unsigned short g_pcodes[NROWS * 8];      // paired codes: p*256+k1*16+k2
__device__ __half         g_plut[8 * 256 * MOUT];   // global paired LUT (4MB, fp16)

// ============================================================
// Kernel 0: build global paired fp16 LUT once; block 2048 also
// computes prototype norms (same fp order as the old prep_pnorm
// kernel -> bit-identical codes) and resets the ticket counter.
// plut[p*256 + k1*16 + k2][m] = rn_fp16( lut[2p][k1][m] + lut[2p+1][k2][m] )
// ============================================================
__global__ void build_plut(const float* __restrict__ luts,
                           const float* __restrict__ protos) {
    if (blockIdx.x == 2048) {            // pnorm + counter-reset block
        int t = threadIdx.x;             // 256 threads: t = c*16 + k
        if (t == 0) g_ctr = 0u;
        const float* p = protos + t * SV;
        float s = 0.f;
#pragma unroll
        for (int i = 0; i < SV; i++) s += p[i] * p[i];
        g_pn[t] = s;
        return;
    }
    const int entry = blockIdx.x;        // p*256 + k12
    const int k12 = entry & 255, p = entry >> 8;
    const int k1 = k12 >> 4, k2 = k12 & 15;
    const int col = threadIdx.x * 4;
    const float4 a = *(const float4*)(luts + ((2 * p) * 16 + k1) * MOUT + col);
    const float4 b = *(const float4*)(luts + ((2 * p + 1) * 16 + k2) * MOUT + col);
    __half2 h0 = __floats2half2_rn(a.x + b.x, a.y + b.y);
    __half2 h1 = __floats2half2_rn(a.z + b.z, a.w + b.w);
    uint2 pk;
    pk.x = *(uint32_t*)&h0;
    pk.y = *(uint32_t*)&h1;
    *(uint2*)(g_plut + (size_t)entry * MOUT + col) = pk;
}

// ============================================================
// Kernel 1: encode. Block = 512 threads, 32 rows per block.
// Hot loop byte-identical to the proven 96.8us version.
// Tail: last-finished block (atomic ticket) performs the global
// scale reduction in the exact order of the old reduce_kernel
// (bit-identical g_scale), saving its 5.5us serial launch.
// ============================================================
#define XCPAD 1156
#define XSPAD 36
#define PTPAD 260
#define ENC_SMEM ((16 * XCPAD + 32 * PTPAD) * 4)

__global__ void __launch_bounds__(512, 2)
encode_kernel(const float* __restrict__ X,
              const float* __restrict__ protos) {
    extern __shared__ float sm[];
    float* Xs = sm;                  // 16 * 1156
    float* Pt = sm + 16 * XCPAD;     // 32 * 260

    __shared__ unsigned char codes_s[32 * 16];
    __shared__ float red[16];
    __shared__ unsigned int isLast;

    const int tid  = threadIdx.x;    // 512
    const int row0 = blockIdx.x * 32;

    // --- stage X tile: 4096 float4-slots (4 rows each), coalesced LDG ---
    float lsum = 0.f;
#pragma unroll
    for (int it = 0; it < 8; it++) {
        int slot = tid + it * 512;       // < 4096
        int d  = slot & 511;
        int r4 = slot >> 9;              // row group 0..7
        int c  = d >> 5, s = d & 31;
        const float* xp = X + (size_t)(row0 + r4 * 4) * DDIM + d;
        float v0 = xp[0];
        float v1 = xp[DDIM];
        float v2 = xp[2 * DDIM];
        float v3 = xp[3 * DDIM];
        lsum += (v0 + v1) + (v2 + v3);
        *(float4*)(Xs + c * XCPAD + s * XSPAD + r4 * 4) =
            make_float4(v0, v1, v2, v3);
    }
    // --- stage protos transposed [s][c][k] ---
#pragma unroll
    for (int it = 0; it < 16; it++) {
        int i = tid + it * 512;          // < 8192
        int c = i >> 9, k = (i >> 5) & 15, s = i & 31;
        Pt[s * PTPAD + c * 16 + k] = protos[i];
    }
    __syncthreads();

    // --- main dot products: thread = (kg, c, rg) -> 4 rows x 4 ks ---
    const int kg = tid & 3;              // codeword group (4 ks)
    const int c  = (tid >> 2) & 15;      // codebook
    const int rg = tid >> 6;             // row group 0..7

    float pnl[4];
#pragma unroll
    for (int kk = 0; kk < 4; kk++) pnl[kk] = g_pn[c * 16 + kg * 4 + kk];

    float acc[4][4];
#pragma unroll
    for (int r = 0; r < 4; r++)
#pragma unroll
        for (int kk = 0; kk < 4; kk++) acc[r][kk] = 0.f;

    const float* xb = Xs + c * XCPAD + rg * 4;
    const float* pb = Pt + c * 16 + kg * 4;

#pragma unroll
    for (int s = 0; s < 32; s++) {
        const float4 xv = *(const float4*)(xb + s * XSPAD);
        const float4 pv = *(const float4*)(pb + s * PTPAD);
        acc[0][0] = fmaf(xv.x, pv.x, acc[0][0]);
        acc[0][1] = fmaf(xv.x, pv.y, acc[0][1]);
        acc[0][2] = fmaf(xv.x, pv.z, acc[0][2]);
        acc[0][3] = fmaf(xv.x, pv.w, acc[0][3]);
        acc[1][0] = fmaf(xv.y, pv.x, acc[1][0]);
        acc[1][1] = fmaf(xv.y, pv.y, acc[1][1]);
        acc[1][2] = fmaf(xv.y, pv.z, acc[1][2]);
        acc[1][3] = fmaf(xv.y, pv.w, acc[1][3]);
        acc[2][0] = fmaf(xv.z, pv.x, acc[2][0]);
        acc[2][1] = fmaf(xv.z, pv.y, acc[2][1]);
        acc[2][2] = fmaf(xv.z, pv.z, acc[2][2]);
        acc[2][3] = fmaf(xv.z, pv.w, acc[2][3]);
        acc[3][0] = fmaf(xv.w, pv.x, acc[3][0]);
        acc[3][1] = fmaf(xv.w, pv.y, acc[3][1]);
        acc[3][2] = fmaf(xv.w, pv.z, acc[3][2]);
        acc[3][3] = fmaf(xv.w, pv.w, acc[3][3]);
    }

    // --- argmin per (row, codebook): local then across 4 kg lanes ---
#pragma unroll
    for (int r = 0; r < 4; r++) {
        float bd = pnl[0] - 2.f * acc[r][0];
        int   bk = kg * 4;
#pragma unroll
        for (int kk = 1; kk < 4; kk++) {
            float dd = pnl[kk] - 2.f * acc[r][kk];
            if (dd < bd) { bd = dd; bk = kg * 4 + kk; }
        }
#pragma unroll
        for (int off = 1; off < 4; off <<= 1) {
            float od = __shfl_xor_sync(0xffffffffu, bd, off);
            int   ok = __shfl_xor_sync(0xffffffffu, bk, off);
            if (od < bd || (od == bd && ok < bk)) { bd = od; bk = ok; }
        }
        if (kg == 0)
            codes_s[(rg * 4 + r) * 16 + c] = (unsigned char)bk;
    }

    // --- deterministic block reduction of lsum (512 thr = 16 warps) ---
#pragma unroll
    for (int off = 16; off; off >>= 1)
        lsum += __shfl_xor_sync(0xffffffffu, lsum, off);
    if ((tid & 31) == 0) red[tid >> 5] = lsum;
    __syncthreads();                      // also publishes codes_s
    if (tid < 16) {
        float v = red[tid];
        v += __shfl_xor_sync(0xffffu, v, 1);
        v += __shfl_xor_sync(0xffffu, v, 2);
        v += __shfl_xor_sync(0xffffu, v, 4);
        v += __shfl_xor_sync(0xffffu, v, 8);
        if (tid == 0) g_bsums[blockIdx.x] = v;
    }

    // --- build paired codes: entry = p*256 + k1*16 + k2 (u16) ---
    if (tid < 256) {
        int r = tid >> 3, p = tid & 7;
        int k1 = codes_s[r * 16 + 2 * p];
        int k2 = codes_s[r * 16 + 2 * p + 1];
        g_pcodes[(row0 + r) * 8 + p] =
            (unsigned short)(p * 256 + k1 * 16 + k2);
    }

    // --- last-block global scale reduction (replaces reduce_kernel) ---
    if (tid == 0) {
        __threadfence();                 // publish g_bsums[blockIdx.x]
        unsigned int t = atomicAdd(&g_ctr, 1u);
        isLast = (t == gridDim.x - 1) ? 1u : 0u;
    }
    __syncthreads();
    if (isLast && tid < 256) {
        // EXACT order of the old reduce_kernel -> bit-identical g_scale
        float s = 0.f;
        for (int i = tid; i < 1024; i += 256) s += g_bsums[i];
#pragma unroll
        for (int off = 16; off; off >>= 1)
            s += __shfl_xor_sync(0xffffffffu, s, off);
        if ((tid & 31) == 0) red[tid >> 5] = s;  // reuse red[]
        __syncwarp();
    }
    __syncthreads();
    if (isLast && tid < 8) {
        float v = red[tid];
        v += __shfl_xor_sync(0xffu, v, 1);
        v += __shfl_xor_sync(0xffu, v, 2);
        v += __shfl_xor_sync(0xffu, v, 4);
        if (tid == 0) g_scale = v * (1.0f / (float)(NROWS * DDIM));
    }
}

// ============================================================
// Kernel 2: paired-LUT accumulate. (byte-identical hot loop to
// the 96.8us version)
// Grid (32 m-tiles of 32 cols, 16 row chunks of 2048 rows).
// ============================================================
#define ACC_SMEM (8 * 256 * 32 * 2)      // 128KB

__global__ void accum_kernel(float* __restrict__ out) {
    extern __shared__ __half plutH[];    // [2048 entries][32 cols]

    const int tid = threadIdx.x;         // 1024
    const int m0  = blockIdx.x * 32;

    // --- copy plut slice: 2048 entries x 64B, strided from gmem ---
#pragma unroll
    for (int it = 0; it < 8; it++) {
        int i = tid + it * 1024;         // < 8192
        int e = i >> 2, g = i & 3;       // entry, 16B group
        *(uint4*)(plutH + e * 32 + g * 8) =
            *(const uint4*)(g_plut + (size_t)e * MOUT + m0 + g * 8);
    }
    __syncthreads();

    const float scale = g_scale;
    const int mg = tid & 3;              // 8-col group within 32-col tile
    const int rl = tid >> 2;             // 256 rows in flight
    const int rowBase = blockIdx.y * 2048 + rl;
    const __half* lutBase = plutH + mg * 8;   // mg*16 bytes

#pragma unroll
    for (int half = 0; half < 2; half++) {
        // --- prefetch 4 rows' pair-codes (MLP=4) ---
        uint4 cw4[4];
#pragma unroll
        for (int rr = 0; rr < 4; rr++)
            cw4[rr] = *(const uint4*)(
                g_pcodes + (size_t)(rowBase + (half * 4 + rr) * 256) * 8);

#pragma unroll
        for (int rr = 0; rr < 4; rr++) {
            const int row = rowBase + (half * 4 + rr) * 256;
            const uint32_t w[4] = {cw4[rr].x, cw4[rr].y, cw4[rr].z, cw4[rr].w};

            __half2 a0 = __half2half2(__ushort_as_half(0));
            __half2 a1 = a0, a2 = a0, a3 = a0;
#pragma unroll
            for (int p = 0; p < 8; p++) {
                uint32_t ww = w[p >> 1];
                uint32_t e  = (p & 1) ? (ww >> 16) : (ww & 0xFFFFu);
                const uint4 v = *(const uint4*)(lutBase + (e << 5));
                a0 = __hadd2(a0, *(const __half2*)&v.x);
                a1 = __hadd2(a1, *(const __half2*)&v.y);
                a2 = __hadd2(a2, *(const __half2*)&v.z);
                a3 = __hadd2(a3, *(const __half2*)&v.w);
            }
            const float2 f0 = __half22float2(a0);
            const float2 f1 = __half22float2(a1);
            const float2 f2 = __half22float2(a2);
            const float2 f3 = __half22float2(a3);
            float* op = out + (size_t)row * MOUT + m0 + mg * 8;
            float4 o1, o2;
            o1.x = f0.x * scale; o1.y = f0.y * scale;
            o1.z = f1.x * scale; o1.w = f1.y * scale;
            o2.x = f2.x * scale; o2.y = f2.y * scale;
            o2.z = f3.x * scale; o2.w = f3.y * scale;
            __stcs((float4*)op, o1);
            __stcs((float4*)(op + 4), o2);
        }
    }
}

// ============================================================
extern "C" void kernel_launch(void* const* d_in, const int* in_sizes, int n_in,
                              void* d_out, int out_size) {
    const float* X      = (const float*)d_in[0];   // [32768, 512]
    const float* protos = (const float*)d_in[1];   // [16, 16, 32]
    const float* luts   = (const float*)d_in[2];   // [16, 16, 1024]
    float* out = (float*)d_out;                    // [32768, 1024]

    cudaFuncSetAttribute(encode_kernel,
        cudaFuncAttributeMaxDynamicSharedMemorySize, ENC_SMEM);
    cudaFuncSetAttribute(accum_kernel,
        cudaFuncAttributeMaxDynamicSharedMemorySize, ACC_SMEM);

    build_plut<<<2049, 256>>>(luts, protos);
    encode_kernel<<<NROWS / 32, 512, ENC_SMEM>>>(X, protos);
    accum_kernel<<<dim3(32, 16), 1024, ACC_SMEM>>>(out);
}

// round 13
// speedup vs baseline: 1.0350x; 1.0350x over previous
#include <cuda_runtime.h>
#include <cuda_fp16.h>
#include <cstdint>

// Problem constants
#define NROWS 32768
#define DDIM  512
#define CB    16     // codebooks
#define KC    16     // codewords per codebook
#define SV    32     // subvector length
#define MOUT  1024

// ---- device scratch (no allocations allowed) ----
__device__ float          g_pn[CB * KC];            // ||proto||^2
__device__ float          g_bsums[1024];            // per-block X sums
__device__ float          g_scale;                  // mean(X)
__device__ unsigned short g_pcodes[NROWS * 8];      // paired codes: p*256+k1*16+k2
__device__ __half         g_plut[8 * 256 * MOUT];   // global paired LUT (4MB, fp16)

// ============================================================
// Kernel 0: prototype squared norms. 1 block x 256 threads.
// ============================================================
__global__ void prep_pnorm(const float* __restrict__ protos) {
    int t = threadIdx.x;                 // t = c*16 + k
    const float* p = protos + t * SV;
    float s = 0.f;
#pragma unroll
    for (int i = 0; i < SV; i++) s += p[i] * p[i];
    g_pn[t] = s;
}

// ============================================================
// Kernel 0b: build global paired fp16 LUT once.
// plut[p*256 + k1*16 + k2][m] = rn_fp16( lut[2p][k1][m] + lut[2p+1][k2][m] )
// Grid 2048 blocks (one per entry) x 256 threads (4 cols each).
// ============================================================
__global__ void build_plut(const float* __restrict__ luts) {
    const int entry = blockIdx.x;        // p*256 + k12
    const int k12 = entry & 255, p = entry >> 8;
    const int k1 = k12 >> 4, k2 = k12 & 15;
    const int col = threadIdx.x * 4;
    const float4 a = *(const float4*)(luts + ((2 * p) * 16 + k1) * MOUT + col);
    const float4 b = *(const float4*)(luts + ((2 * p + 1) * 16 + k2) * MOUT + col);
    __half2 h0 = __floats2half2_rn(a.x + b.x, a.y + b.y);
    __half2 h1 = __floats2half2_rn(a.z + b.z, a.w + b.w);
    uint2 pk;
    pk.x = *(uint32_t*)&h0;
    pk.y = *(uint32_t*)&h1;
    *(uint2*)(g_plut + (size_t)entry * MOUT + col) = pk;
}

// ============================================================
// Kernel 1: encode. Block = 512 threads, 32 rows per block.
// (Exact proven-96.8us version: numerics and layout untouched.)
// ============================================================
#define XCPAD 1156
#define XSPAD 36
#define PTPAD 260
#define ENC_SMEM ((16 * XCPAD + 32 * PTPAD) * 4)

__global__ void __launch_bounds__(512, 2)
encode_kernel(const float* __restrict__ X,
              const float* __restrict__ protos) {
    extern __shared__ float sm[];
    float* Xs = sm;                  // 16 * 1156
    float* Pt = sm + 16 * XCPAD;     // 32 * 260

    __shared__ unsigned char codes_s[32 * 16];
    __shared__ float red[16];

    const int tid  = threadIdx.x;    // 512
    const int row0 = blockIdx.x * 32;

    // --- stage X tile: 4096 float4-slots (4 rows each), coalesced LDG ---
    float lsum = 0.f;
#pragma unroll
    for (int it = 0; it < 8; it++) {
        int slot = tid + it * 512;       // < 4096
        int d  = slot & 511;
        int r4 = slot >> 9;              // row group 0..7
        int c  = d >> 5, s = d & 31;
        const float* xp = X + (size_t)(row0 + r4 * 4) * DDIM + d;
        float v0 = xp[0];
        float v1 = xp[DDIM];
        float v2 = xp[2 * DDIM];
        float v3 = xp[3 * DDIM];
        lsum += (v0 + v1) + (v2 + v3);
        *(float4*)(Xs + c * XCPAD + s * XSPAD + r4 * 4) =
            make_float4(v0, v1, v2, v3);
    }
    // --- stage protos transposed [s][c][k] ---
#pragma unroll
    for (int it = 0; it < 16; it++) {
        int i = tid + it * 512;          // < 8192
        int c = i >> 9, k = (i >> 5) & 15, s = i & 31;
        Pt[s * PTPAD + c * 16 + k] = protos[i];
    }
    __syncthreads();

    // --- main dot products: thread = (kg, c, rg) -> 4 rows x 4 ks ---
    const int kg = tid & 3;              // codeword group (4 ks)
    const int c  = (tid >> 2) & 15;      // codebook
    const int rg = tid >> 6;             // row group 0..7

    float pnl[4];
#pragma unroll
    for (int kk = 0; kk < 4; kk++) pnl[kk] = g_pn[c * 16 + kg * 4 + kk];

    float acc[4][4];
#pragma unroll
    for (int r = 0; r < 4; r++)
#pragma unroll
        for (int kk = 0; kk < 4; kk++) acc[r][kk] = 0.f;

    const float* xb = Xs + c * XCPAD + rg * 4;
    const float* pb = Pt + c * 16 + kg * 4;

#pragma unroll
    for (int s = 0; s < 32; s++) {
        const float4 xv = *(const float4*)(xb + s * XSPAD);
        const float4 pv = *(const float4*)(pb + s * PTPAD);
        acc[0][0] = fmaf(xv.x, pv.x, acc[0][0]);
        acc[0][1] = fmaf(xv.x, pv.y, acc[0][1]);
        acc[0][2] = fmaf(xv.x, pv.z, acc[0][2]);
        acc[0][3] = fmaf(xv.x, pv.w, acc[0][3]);
        acc[1][0] = fmaf(xv.y, pv.x, acc[1][0]);
        acc[1][1] = fmaf(xv.y, pv.y, acc[1][1]);
        acc[1][2] = fmaf(xv.y, pv.z, acc[1][2]);
        acc[1][3] = fmaf(xv.y, pv.w, acc[1][3]);
        acc[2][0] = fmaf(xv.z, pv.x, acc[2][0]);
        acc[2][1] = fmaf(xv.z, pv.y, acc[2][1]);
        acc[2][2] = fmaf(xv.z, pv.z, acc[2][2]);
        acc[2][3] = fmaf(xv.z, pv.w, acc[2][3]);
        acc[3][0] = fmaf(xv.w, pv.x, acc[3][0]);
        acc[3][1] = fmaf(xv.w, pv.y, acc[3][1]);
        acc[3][2] = fmaf(xv.w, pv.z, acc[3][2]);
        acc[3][3] = fmaf(xv.w, pv.w, acc[3][3]);
    }

    // --- argmin per (row, codebook): local then across 4 kg lanes ---
#pragma unroll
    for (int r = 0; r < 4; r++) {
        float bd = pnl[0] - 2.f * acc[r][0];
        int   bk = kg * 4;
#pragma unroll
        for (int kk = 1; kk < 4; kk++) {
            float dd = pnl[kk] - 2.f * acc[r][kk];
            if (dd < bd) { bd = dd; bk = kg * 4 + kk; }
        }
#pragma unroll
        for (int off = 1; off < 4; off <<= 1) {
            float od = __shfl_xor_sync(0xffffffffu, bd, off);
            int   ok = __shfl_xor_sync(0xffffffffu, bk, off);
            if (od < bd || (od == bd && ok < bk)) { bd = od; bk = ok; }
        }
        if (kg == 0)
            codes_s[(rg * 4 + r) * 16 + c] = (unsigned char)bk;
    }

    // --- deterministic block reduction of lsum (512 thr = 16 warps) ---
#pragma unroll
    for (int off = 16; off; off >>= 1)
        lsum += __shfl_xor_sync(0xffffffffu, lsum, off);
    if ((tid & 31) == 0) red[tid >> 5] = lsum;
    __syncthreads();                      // also publishes codes_s
    if (tid < 16) {
        float v = red[tid];
        v += __shfl_xor_sync(0xffffu, v, 1);
        v += __shfl_xor_sync(0xffffu, v, 2);
        v += __shfl_xor_sync(0xffffu, v, 4);
        v += __shfl_xor_sync(0xffffu, v, 8);
        if (tid == 0) g_bsums[blockIdx.x] = v;
    }

    // --- build paired codes: entry = p*256 + k1*16 + k2 (u16) ---
    if (tid < 256) {
        int r = tid >> 3, p = tid & 7;
        int k1 = codes_s[r * 16 + 2 * p];
        int k2 = codes_s[r * 16 + 2 * p + 1];
        g_pcodes[(row0 + r) * 8 + p] =
            (unsigned short)(p * 256 + k1 * 16 + k2);
    }
}

// ============================================================
// Kernel 2: reduce block sums -> g_scale = mean(X). 1 block.
// ============================================================
__global__ void reduce_kernel() {
    const int tid = threadIdx.x;         // 256 threads
    float s = 0.f;
    for (int i = tid; i < 1024; i += 256) s += g_bsums[i];
    __shared__ float red[8];
#pragma unroll
    for (int off = 16; off; off >>= 1)
        s += __shfl_xor_sync(0xffffffffu, s, off);
    if ((tid & 31) == 0) red[tid >> 5] = s;
    __syncthreads();
    if (tid < 8) {
        float v = red[tid];
        v += __shfl_xor_sync(0xffu, v, 1);
        v += __shfl_xor_sync(0xffu, v, 2);
        v += __shfl_xor_sync(0xffu, v, 4);
        if (tid == 0) g_scale = v * (1.0f / (float)(NROWS * DDIM));
    }
}

// ============================================================
// Kernel 3: paired-LUT accumulate with XOR-swizzled smem plut.
// Chunk g (16B) of entry e lives at slot g ^ x(e), where
// x(e) = (e ^ e>>2 ^ e>>4) & 3. Gather reads slot mg ^ x(e):
// bank-window equality now needs (parity AND x) equal -> pair
// collision P drops 1/2 -> 1/8, E[phase cost] ~1.9x -> ~1.4x.
// Grid (32 m-tiles of 32 cols, 16 row chunks of 2048 rows).
// ============================================================
#define ACC_SMEM (8 * 256 * 32 * 2)      // 128KB

__global__ void accum_kernel(float* __restrict__ out) {
    extern __shared__ __half plutH[];    // [2048 entries][32 cols], swizzled

    const int tid = threadIdx.x;         // 1024
    const int m0  = blockIdx.x * 32;

    // --- copy plut slice: 2048 entries x 64B, swizzled STS ---
#pragma unroll
    for (int it = 0; it < 8; it++) {
        int i = tid + it * 1024;         // < 8192
        int e = i >> 2, g = i & 3;       // entry, 16B chunk
        int x = (e ^ (e >> 2) ^ (e >> 4)) & 3;
        *(uint4*)(plutH + e * 32 + ((g ^ x) << 3)) =
            *(const uint4*)(g_plut + (size_t)e * MOUT + m0 + g * 8);
    }
    __syncthreads();

    const float scale = g_scale;
    const int mg = tid & 3;              // 8-col group within 32-col tile
    const int rl = tid >> 2;             // 256 rows in flight
    const int rowBase = blockIdx.y * 2048 + rl;

#pragma unroll
    for (int half = 0; half < 2; half++) {
        // --- prefetch 4 rows' pair-codes (MLP=4) ---
        uint4 cw4[4];
#pragma unroll
        for (int rr = 0; rr < 4; rr++)
            cw4[rr] = *(const uint4*)(
                g_pcodes + (size_t)(rowBase + (half * 4 + rr) * 256) * 8);

#pragma unroll
        for (int rr = 0; rr < 4; rr++) {
            const int row = rowBase + (half * 4 + rr) * 256;
            const uint32_t w[4] = {cw4[rr].x, cw4[rr].y, cw4[rr].z, cw4[rr].w};

            __half2 a0 = __half2half2(__ushort_as_half(0));
            __half2 a1 = a0, a2 = a0, a3 = a0;
#pragma unroll
            for (int p = 0; p < 8; p++) {
                uint32_t ww = w[p >> 1];
                uint32_t e  = (p & 1) ? (ww >> 16) : (ww & 0xFFFFu);
                uint32_t x  = (e ^ (e >> 2) ^ (e >> 4)) & 3u;
                const uint4 v = *(const uint4*)(
                    plutH + (e << 5) + (((uint32_t)mg ^ x) << 3));
                a0 = __hadd2(a0, *(const __half2*)&v.x);
                a1 = __hadd2(a1, *(const __half2*)&v.y);
                a2 = __hadd2(a2, *(const __half2*)&v.z);
                a3 = __hadd2(a3, *(const __half2*)&v.w);
            }
            const float2 f0 = __half22float2(a0);
            const float2 f1 = __half22float2(a1);
            const float2 f2 = __half22float2(a2);
            const float2 f3 = __half22float2(a3);
            float* op = out + (size_t)row * MOUT + m0 + mg * 8;
            float4 o1, o2;
            o1.x = f0.x * scale; o1.y = f0.y * scale;
            o1.z = f1.x * scale; o1.w = f1.y * scale;
            o2.x = f2.x * scale; o2.y = f2.y * scale;
            o2.z = f3.x * scale; o2.w = f3.y * scale;
            __stcs((float4*)op, o1);
            __stcs((float4*)(op + 4), o2);
        }
    }
}

// ============================================================
extern "C" void kernel_launch(void* const* d_in, const int* in_sizes, int n_in,
                              void* d_out, int out_size) {
    const float* X      = (const float*)d_in[0];   // [32768, 512]
    const float* protos = (const float*)d_in[1];   // [16, 16, 32]
    const float* luts   = (const float*)d_in[2];   // [16, 16, 1024]
    float* out = (float*)d_out;                    // [32768, 1024]

    cudaFuncSetAttribute(encode_kernel,
        cudaFuncAttributeMaxDynamicSharedMemorySize, ENC_SMEM);
    cudaFuncSetAttribute(accum_kernel,
        cudaFuncAttributeMaxDynamicSharedMemorySize, ACC_SMEM);

    prep_pnorm<<<1, 256>>>(protos);
    build_plut<<<2048, 256>>>(luts);
    encode_kernel<<<NROWS / 32, 512, ENC_SMEM>>>(X, protos);
    reduce_kernel<<<1, 256>>>();
    accum_kernel<<<dim3(32, 16), 1024, ACC_SMEM>>>(out);
}